// round 14
// baseline (speedup 1.0000x reference)
#include <cuda_runtime.h>

#define THREADS 128
#define NW 4           // warps per block, one warp per path
#define NBLOCKS 1024   // 4096 paths
#define DXSTRIDE 16    // floats/step: 5 dup pairs (10) + pad + 4 scalars, 64B
#define DXROW (127 * DXSTRIDE + 16)

// Signature layout (d=5, depth 4): L1 [0,5) L2 [5,30) L3 [30,155) L4 [155,780)
__device__ double g_acc[2][784];

typedef unsigned long long ull;

__device__ __forceinline__ ull pk2(float lo, float hi) {
    ull r; asm("mov.b64 %0, {%1,%2};" : "=l"(r) : "f"(lo), "f"(hi)); return r;
}
__device__ __forceinline__ void unpk2(ull v, float& a, float& b) {
    asm("mov.b64 {%0,%1}, %2;" : "=f"(a), "=f"(b) : "l"(v));
}
__device__ __forceinline__ ull fma2v(ull a, ull b, ull c) {
    ull d; asm("fma.rn.f32x2 %0, %1, %2, %3;" : "=l"(d) : "l"(a), "l"(b), "l"(c));
    return d;
}

__global__ void __launch_bounds__(THREADS, 6) sig_kernel(
    const float* __restrict__ xin,
    const float* __restrict__ yin,
    const float* __restrict__ sigma)
{
    // per-warp increments, stride 16 floats (64B) per step:
    //   [0..9]  : (d_c, d_c) duplicate pairs, c = 0..4  -> 2x LDS.128 + LDS.64
    //   [12..15]: scalars d0..d3 ONLY (c=4 would hit slot 16 = next step's D0)
    __shared__ __align__(16) float dxs[NW][DXROW];
    __shared__ float shacc[784];

    const int tid  = threadIdx.x;
    const int lane = tid & 31;
    const int wib  = tid >> 5;
    const int gw   = blockIdx.x * NW + wib;  // path id 0..4095
    const int set  = gw >> 11;               // 0: x (sigma-scaled), 1: y
    const int bidx = gw & 2047;

    for (int i = tid; i < 784; i += THREADS) shacc[i] = 0.0f;
    __syncthreads();

    float* dx = dxs[wib];
    const float* path = (set == 0 ? xin : yin) + (size_t)bidx * 640;

    const float sc1 = (set == 0) ? __ldg(sigma + 0) : 1.0f;
    const float sc2 = (set == 0) ? __ldg(sigma + 1) : 1.0f;
    const float sc3 = (set == 0) ? __ldg(sigma + 2) : 1.0f;
    const float sc4 = (set == 0) ? __ldg(sigma + 3) : 1.0f;

    // stage: dup pair (STS.64) always; scalar copy (STS.32) only for c<4
    for (int i = lane; i < 635; i += 32) {
        int t = i / 5;
        int c = i - 5 * t;
        float s = (c == 0) ? 1.0f : (c == 1) ? sc1 : (c == 2) ? sc2
                : (c == 3) ? sc3 : sc4;
        float v = (path[i + 5] - path[i]) * s;
        *reinterpret_cast<ull*>(&dx[DXSTRIDE * t + 2 * c]) = pk2(v, v);
        if (c < 4) dx[DXSTRIDE * t + 12 + c] = v;  // d4 scalar comes from D4 dup
    }
    __syncwarp();

    // --- lane = level-2 index ab (lanes 0..24 active; 25..31 clone lane 24) --
    const int lc = (lane < 25) ? lane : 24;
    const int a  = lc / 5;
    const int b  = lc - 5 * a;
    // scalar-region offsets for dxa/dxb (d4 scalar lives at dup slot 8)
    const int offa = (a < 4) ? (12 + a) : 8;
    const int offb = (b < 4) ? (12 + b) : 8;

    // state: S1[a], S2[ab], S3[5ab+c] (c-packed), S4[25ab+5c+e]
    float s1 = 0.f, s2 = 0.f, s3_4 = 0.f, s4C4 = 0.f;
    ull s3_01 = 0, s3_23 = 0, s4C01 = 0, s4C23 = 0;
    ull s4A[5], s4B[5];
#pragma unroll
    for (int e = 0; e < 5; ++e) { s4A[e] = 0ULL; s4B[e] = 0ULL; }

    // unroll 2: two independent step bodies let ptxas overlap step t+1's
    // LDS latency with step t's FMA tail (loop-carried deps are 1 FMA each)
#pragma unroll 2
    for (int t = 0; t < 127; ++t) {
        const float* dxt = dx + DXSTRIDE * t;
        // dup pairs: two LDS.128 + one LDS.64 (no pk2/unpk2 needed)
        const ulonglong2 D01 = *reinterpret_cast<const ulonglong2*>(dxt + 0);
        const ulonglong2 D23 = *reinterpret_cast<const ulonglong2*>(dxt + 4);
        const ull D0 = D01.x, D1 = D01.y, D2 = D23.x, D3 = D23.y;
        const ull D4 = *reinterpret_cast<const ull*>(dxt + 8);
        // scalar quad d0..d3: one LDS.128
        const float4 sq = *reinterpret_cast<const float4*>(dxt + 12);
        float d4, j_; unpk2(D4, d4, j_);
        const ull d01 = pk2(sq.x, sq.y);
        const ull d23 = pk2(sq.z, sq.w);
        const float dxa = dxt[offa];
        const float dxb = dxt[offb];

        // level-1 + level-2 helpers (scalar; imm multipliers -> rt-1 FFMA)
        const float a1 = fmaf(dxa, 0.25f,      s1);
        const float c1 = fmaf(dxa, (1.f/3.f),  s1);
        const float e1 = fmaf(dxa, 0.5f,       s1);
        s1 += dxa;
        const float a2  = fmaf(a1 * (1.f/3.f), dxb, s2);
        const float a2h = 0.5f * a2;
        const float b2  = fmaf(c1 * 0.5f, dxb, s2);
        s2 = fmaf(e1, dxb, s2);

        const ull a2hd = pk2(a2h, a2h);
        const ull b2d  = pk2(b2,  b2);

        // level-3: a3_c = a2h*dx[c] + S3[c];  S3[c] += b2*dx[c]
        const ull a3_01 = fma2v(a2hd, d01, s3_01);
        const ull a3_23 = fma2v(a2hd, d23, s3_23);
        s3_01 = fma2v(b2d, d01, s3_01);
        s3_23 = fma2v(b2d, d23, s3_23);
        const float a3_4 = fmaf(a2h, d4, s3_4);
        s3_4 = fmaf(b2, d4, s3_4);

        // level-4: S4[c][e] += a3_c * dx[e]  (packed over c-pairs)
        s4A[0] = fma2v(a3_01, D0, s4A[0]);
        s4A[1] = fma2v(a3_01, D1, s4A[1]);
        s4A[2] = fma2v(a3_01, D2, s4A[2]);
        s4A[3] = fma2v(a3_01, D3, s4A[3]);
        s4A[4] = fma2v(a3_01, D4, s4A[4]);
        s4B[0] = fma2v(a3_23, D0, s4B[0]);
        s4B[1] = fma2v(a3_23, D1, s4B[1]);
        s4B[2] = fma2v(a3_23, D2, s4B[2]);
        s4B[3] = fma2v(a3_23, D3, s4B[3]);
        s4B[4] = fma2v(a3_23, D4, s4B[4]);
        const ull a3_4d = pk2(a3_4, a3_4);
        s4C01 = fma2v(a3_4d, d01, s4C01);
        s4C23 = fma2v(a3_4d, d23, s4C23);
        s4C4  = fmaf(a3_4, d4, s4C4);
    }

    // --- block reduction: shared float atomics (distinct addrs per lane) ---
    if (lane < 25) {
        if (b == 0) atomicAdd(&shacc[a], s1);          // lanes 0,5,10,15,20
        atomicAdd(&shacc[5 + lane], s2);
        float v0, v1, v2, v3;
        unpk2(s3_01, v0, v1); unpk2(s3_23, v2, v3);
        const int b3 = 30 + 5 * lane;
        atomicAdd(&shacc[b3 + 0], v0);
        atomicAdd(&shacc[b3 + 1], v1);
        atomicAdd(&shacc[b3 + 2], v2);
        atomicAdd(&shacc[b3 + 3], v3);
        atomicAdd(&shacc[b3 + 4], s3_4);
        const int b4 = 155 + 25 * lane;
#pragma unroll
        for (int e = 0; e < 5; ++e) {
            float x0, x1, y0, y1;
            unpk2(s4A[e], x0, x1);
            unpk2(s4B[e], y0, y1);
            atomicAdd(&shacc[b4 + 0  + e], x0);   // c = 0
            atomicAdd(&shacc[b4 + 5  + e], x1);   // c = 1
            atomicAdd(&shacc[b4 + 10 + e], y0);   // c = 2
            atomicAdd(&shacc[b4 + 15 + e], y1);   // c = 3
        }
        float z0, z1, z2, z3;
        unpk2(s4C01, z0, z1); unpk2(s4C23, z2, z3);
        atomicAdd(&shacc[b4 + 20], z0);
        atomicAdd(&shacc[b4 + 21], z1);
        atomicAdd(&shacc[b4 + 22], z2);
        atomicAdd(&shacc[b4 + 23], z3);
        atomicAdd(&shacc[b4 + 24], s4C4);
    }
    __syncthreads();

    // global: double atomics, 1024 contributions per address
    for (int i = tid; i < 780; i += THREADS)
        atomicAdd(&g_acc[set][i], (double)shacc[i]);
}

// one element per thread + warp-shuffle reduce; resets g_acc for next replay
__global__ void finalize_kernel(float* out) {
    __shared__ double wred[32];
    const int tid  = threadIdx.x;     // 1024 threads = 32 warps
    const int lane = tid & 31;
    const int wid  = tid >> 5;

    double s = 0.0;
    if (tid < 780) {
        double d = (g_acc[0][tid] - g_acc[1][tid]) * (1.0 / 2048.0);
        s = d * d;
    }
#pragma unroll
    for (int k = 16; k > 0; k >>= 1)
        s += __shfl_down_sync(0xffffffffu, s, k);
    if (lane == 0) wred[wid] = s;
    __syncthreads();
    if (wid == 0) {
        double v = wred[lane];
#pragma unroll
        for (int k = 16; k > 0; k >>= 1)
            v += __shfl_down_sync(0xffffffffu, v, k);
        if (lane == 0) out[0] = (float)v;
    }
    // reset accumulators (2 passes over 1568 doubles)
    for (int e = tid; e < 2 * 784; e += 1024)
        ((double*)g_acc)[e] = 0.0;
}

extern "C" void kernel_launch(void* const* d_in, const int* in_sizes, int n_in,
                              void* d_out, int out_size) {
    (void)in_sizes; (void)n_in; (void)out_size;
    const float* x     = (const float*)d_in[0];
    const float* y     = (const float*)d_in[1];
    const float* sigma = (const float*)d_in[2];
    float* out = (float*)d_out;

    sig_kernel<<<NBLOCKS, THREADS>>>(x, y, sigma);
    finalize_kernel<<<1, 1024>>>(out);
}

// round 15
// speedup vs baseline: 1.0672x; 1.0672x over previous
#include <cuda_runtime.h>

#define THREADS 128
#define NW 4           // warps per block, one warp per path
#define NBLOCKS 1024   // 4096 paths
#define DXSTRIDE 16    // floats/step: 5 dup pairs (10) + pad + 4 scalars, 64B
#define DXROW (127 * DXSTRIDE + 16)

// Signature layout (d=5, depth 4): L1 [0,5) L2 [5,30) L3 [30,155) L4 [155,780)
__device__ double g_acc[2][784];

typedef unsigned long long ull;

__device__ __forceinline__ ull pk2(float lo, float hi) {
    ull r; asm("mov.b64 %0, {%1,%2};" : "=l"(r) : "f"(lo), "f"(hi)); return r;
}
__device__ __forceinline__ void unpk2(ull v, float& a, float& b) {
    asm("mov.b64 {%0,%1}, %2;" : "=f"(a), "=f"(b) : "l"(v));
}
__device__ __forceinline__ ull fma2v(ull a, ull b, ull c) {
    ull d; asm("fma.rn.f32x2 %0, %1, %2, %3;" : "=l"(d) : "l"(a), "l"(b), "l"(c));
    return d;
}

__global__ void __launch_bounds__(THREADS, 6) sig_kernel(
    const float* __restrict__ xin,
    const float* __restrict__ yin,
    const float* __restrict__ sigma)
{
    // per-warp increments, stride 16 floats (64B) per step:
    //   [0..9]  : (d_c, d_c) duplicate pairs, c = 0..4  -> 2x LDS.128 + LDS.64
    //   [12..15]: scalars d0..d3 ONLY (c=4 would hit slot 16 = next step's D0)
    __shared__ __align__(16) float dxs[NW][DXROW];
    __shared__ float shacc[784];

    const int tid  = threadIdx.x;
    const int lane = tid & 31;
    const int wib  = tid >> 5;
    const int gw   = blockIdx.x * NW + wib;  // path id 0..4095
    const int set  = gw >> 11;               // 0: x (sigma-scaled), 1: y
    const int bidx = gw & 2047;

    for (int i = tid; i < 784; i += THREADS) shacc[i] = 0.0f;
    __syncthreads();

    float* dx = dxs[wib];
    const float* path = (set == 0 ? xin : yin) + (size_t)bidx * 640;

    const float sc1 = (set == 0) ? __ldg(sigma + 0) : 1.0f;
    const float sc2 = (set == 0) ? __ldg(sigma + 1) : 1.0f;
    const float sc3 = (set == 0) ? __ldg(sigma + 2) : 1.0f;
    const float sc4 = (set == 0) ? __ldg(sigma + 3) : 1.0f;

    // stage: dup pair (STS.64) always; scalar copy (STS.32) only for c<4
    for (int i = lane; i < 635; i += 32) {
        int t = i / 5;
        int c = i - 5 * t;
        float s = (c == 0) ? 1.0f : (c == 1) ? sc1 : (c == 2) ? sc2
                : (c == 3) ? sc3 : sc4;
        float v = (path[i + 5] - path[i]) * s;
        *reinterpret_cast<ull*>(&dx[DXSTRIDE * t + 2 * c]) = pk2(v, v);
        if (c < 4) dx[DXSTRIDE * t + 12 + c] = v;  // d4 scalar comes from D4 dup
    }
    __syncwarp();

    // --- lane = level-2 index ab (lanes 0..24 active; 25..31 clone lane 24) --
    const int lc = (lane < 25) ? lane : 24;
    const int a  = lc / 5;
    const int b  = lc - 5 * a;
    // scalar-region offsets for dxa/dxb (d4 scalar lives at dup slot 8)
    const int offa = (a < 4) ? (12 + a) : 8;
    const int offb = (b < 4) ? (12 + b) : 8;

    // state: S1[a], S2[ab], S3[5ab+c] (c-packed), S4[25ab+5c+e]
    float s1 = 0.f, s2 = 0.f, s3_4 = 0.f, s4C4 = 0.f;
    ull s3_01 = 0, s3_23 = 0, s4C01 = 0, s4C23 = 0;
    ull s4A[5], s4B[5];
#pragma unroll
    for (int e = 0; e < 5; ++e) { s4A[e] = 0ULL; s4B[e] = 0ULL; }

    // rotate dxa/dxb one step ahead: the LDS(29cyc) heading the longest chain
    // (dxa -> a1 -> a2 -> a2h -> a3 -> S4) is issued a full step early.
    float dxa = dx[offa];
    float dxb = dx[offb];

    for (int t = 0; t < 127; ++t) {
        const float* dxt = dx + DXSTRIDE * t;
        // preload next step's chain heads (t=126 reads the in-bounds pad)
        const float dxa_n = dxt[DXSTRIDE + offa];
        const float dxb_n = dxt[DXSTRIDE + offb];

        // dup pairs: two LDS.128 + one LDS.64 (no pk2/unpk2 needed)
        const ulonglong2 D01 = *reinterpret_cast<const ulonglong2*>(dxt + 0);
        const ulonglong2 D23 = *reinterpret_cast<const ulonglong2*>(dxt + 4);
        const ull D0 = D01.x, D1 = D01.y, D2 = D23.x, D3 = D23.y;
        const ull D4 = *reinterpret_cast<const ull*>(dxt + 8);
        // scalar quad d0..d3: one LDS.128
        const float4 sq = *reinterpret_cast<const float4*>(dxt + 12);
        float d4, j_; unpk2(D4, d4, j_);
        const ull d01 = pk2(sq.x, sq.y);
        const ull d23 = pk2(sq.z, sq.w);

        // level-1 + level-2 helpers (scalar; imm multipliers -> rt-1 FFMA)
        const float a1 = fmaf(dxa, 0.25f,      s1);
        const float c1 = fmaf(dxa, (1.f/3.f),  s1);
        const float e1 = fmaf(dxa, 0.5f,       s1);
        s1 += dxa;
        const float a2  = fmaf(a1 * (1.f/3.f), dxb, s2);
        const float a2h = 0.5f * a2;
        const float b2  = fmaf(c1 * 0.5f, dxb, s2);
        s2 = fmaf(e1, dxb, s2);

        const ull a2hd = pk2(a2h, a2h);
        const ull b2d  = pk2(b2,  b2);

        // level-3: a3_c = a2h*dx[c] + S3[c];  S3[c] += b2*dx[c]
        const ull a3_01 = fma2v(a2hd, d01, s3_01);
        const ull a3_23 = fma2v(a2hd, d23, s3_23);
        s3_01 = fma2v(b2d, d01, s3_01);
        s3_23 = fma2v(b2d, d23, s3_23);
        const float a3_4 = fmaf(a2h, d4, s3_4);
        s3_4 = fmaf(b2, d4, s3_4);

        // level-4: S4[c][e] += a3_c * dx[e]  (packed over c-pairs)
        s4A[0] = fma2v(a3_01, D0, s4A[0]);
        s4A[1] = fma2v(a3_01, D1, s4A[1]);
        s4A[2] = fma2v(a3_01, D2, s4A[2]);
        s4A[3] = fma2v(a3_01, D3, s4A[3]);
        s4A[4] = fma2v(a3_01, D4, s4A[4]);
        s4B[0] = fma2v(a3_23, D0, s4B[0]);
        s4B[1] = fma2v(a3_23, D1, s4B[1]);
        s4B[2] = fma2v(a3_23, D2, s4B[2]);
        s4B[3] = fma2v(a3_23, D3, s4B[3]);
        s4B[4] = fma2v(a3_23, D4, s4B[4]);
        const ull a3_4d = pk2(a3_4, a3_4);
        s4C01 = fma2v(a3_4d, d01, s4C01);
        s4C23 = fma2v(a3_4d, d23, s4C23);
        s4C4  = fmaf(a3_4, d4, s4C4);

        dxa = dxa_n;
        dxb = dxb_n;
    }

    // --- block reduction: shared float atomics (distinct addrs per lane) ---
    if (lane < 25) {
        if (b == 0) atomicAdd(&shacc[a], s1);          // lanes 0,5,10,15,20
        atomicAdd(&shacc[5 + lane], s2);
        float v0, v1, v2, v3;
        unpk2(s3_01, v0, v1); unpk2(s3_23, v2, v3);
        const int b3 = 30 + 5 * lane;
        atomicAdd(&shacc[b3 + 0], v0);
        atomicAdd(&shacc[b3 + 1], v1);
        atomicAdd(&shacc[b3 + 2], v2);
        atomicAdd(&shacc[b3 + 3], v3);
        atomicAdd(&shacc[b3 + 4], s3_4);
        const int b4 = 155 + 25 * lane;
#pragma unroll
        for (int e = 0; e < 5; ++e) {
            float x0, x1, y0, y1;
            unpk2(s4A[e], x0, x1);
            unpk2(s4B[e], y0, y1);
            atomicAdd(&shacc[b4 + 0  + e], x0);   // c = 0
            atomicAdd(&shacc[b4 + 5  + e], x1);   // c = 1
            atomicAdd(&shacc[b4 + 10 + e], y0);   // c = 2
            atomicAdd(&shacc[b4 + 15 + e], y1);   // c = 3
        }
        float z0, z1, z2, z3;
        unpk2(s4C01, z0, z1); unpk2(s4C23, z2, z3);
        atomicAdd(&shacc[b4 + 20], z0);
        atomicAdd(&shacc[b4 + 21], z1);
        atomicAdd(&shacc[b4 + 22], z2);
        atomicAdd(&shacc[b4 + 23], z3);
        atomicAdd(&shacc[b4 + 24], s4C4);
    }
    __syncthreads();

    // global: double atomics, 1024 contributions per address
    for (int i = tid; i < 780; i += THREADS)
        atomicAdd(&g_acc[set][i], (double)shacc[i]);
}

// one element per thread + warp-shuffle reduce; resets g_acc for next replay
__global__ void finalize_kernel(float* out) {
    __shared__ double wred[32];
    const int tid  = threadIdx.x;     // 1024 threads = 32 warps
    const int lane = tid & 31;
    const int wid  = tid >> 5;

    double s = 0.0;
    if (tid < 780) {
        double d = (g_acc[0][tid] - g_acc[1][tid]) * (1.0 / 2048.0);
        s = d * d;
    }
#pragma unroll
    for (int k = 16; k > 0; k >>= 1)
        s += __shfl_down_sync(0xffffffffu, s, k);
    if (lane == 0) wred[wid] = s;
    __syncthreads();
    if (wid == 0) {
        double v = wred[lane];
#pragma unroll
        for (int k = 16; k > 0; k >>= 1)
            v += __shfl_down_sync(0xffffffffu, v, k);
        if (lane == 0) out[0] = (float)v;
    }
    // reset accumulators for the next graph replay
    for (int e = tid; e < 2 * 784; e += 1024)
        ((double*)g_acc)[e] = 0.0;
}

extern "C" void kernel_launch(void* const* d_in, const int* in_sizes, int n_in,
                              void* d_out, int out_size) {
    (void)in_sizes; (void)n_in; (void)out_size;
    const float* x     = (const float*)d_in[0];
    const float* y     = (const float*)d_in[1];
    const float* sigma = (const float*)d_in[2];
    float* out = (float*)d_out;

    sig_kernel<<<NBLOCKS, THREADS>>>(x, y, sigma);
    finalize_kernel<<<1, 1024>>>(out);
}